// round 3
// baseline (speedup 1.0000x reference)
#include <cuda_runtime.h>
#include <cstdio>

#define BATCH 64
#define SEQ   512
#define CH    128
#define NHEAD 4
#define DHEAD 32
#define NL    8
#define RNN   256
#define TOK   (BATCH*SEQ)          // 32768

// ---------------- scratch (static __device__, no allocations) ----------------
__device__ float d_xt   [TOK*CH];
__device__ float d_ln   [TOK*CH];
__device__ float d_q    [TOK*CH];
__device__ float d_k    [TOK*CH];
__device__ float d_v    [TOK*512];
__device__ float d_r    [TOK*512];
__device__ float d_rw   [TOK*CH];
__device__ float d_mha  [TOK*CH];
__device__ float d_states[BATCH*NL*CH*SEQ];     // (b, layer, c, k) == (B,1024,512)
__device__ float d_ftmp [BATCH*256*SEQ];
__device__ float d_g    [BATCH*256];
__device__ float d_gb   [BATCH*256];
__device__ float d_pb   [BATCH*256];
__device__ float d_rnn  [BATCH*256*SEQ];
__device__ float d_it   [TOK*256];
__device__ float d_wTih [256*1024];
__device__ float d_wThh [256*1024];
__device__ float d_gates[TOK*1024];
__device__ float d_ocf  [BATCH*256*SEQ];
__device__ float d_p1   [BATCH*256*SEQ];
__device__ float d_p2   [BATCH*64*SEQ];

// ---------------- LayerNorm + transpose: (B,C,K) -> tokens (T,128) ----------
__global__ void ln_kernel(const float* __restrict__ h, long long bStride,
                          const float* __restrict__ gw, const float* __restrict__ bw,
                          float* __restrict__ xt, float* __restrict__ ln)
{
    int warp = threadIdx.x >> 5, lane = threadIdx.x & 31;
    int t = blockIdx.x * 8 + warp;
    int b = t >> 9, k = t & 511;
    const float* base = h + (size_t)b * bStride + k;
    float v[4]; float s = 0.f;
#pragma unroll
    for (int i = 0; i < 4; i++) { int c = lane + 32*i; v[i] = base[(size_t)c*512]; s += v[i]; }
#pragma unroll
    for (int o = 16; o; o >>= 1) s += __shfl_xor_sync(0xffffffffu, s, o);
    float mu = s * (1.f/128.f);
    float var = 0.f;
#pragma unroll
    for (int i = 0; i < 4; i++) { float d = v[i]-mu; var += d*d; }
#pragma unroll
    for (int o = 16; o; o >>= 1) var += __shfl_xor_sync(0xffffffffu, var, o);
    float rs = rsqrtf(var * (1.f/128.f) + 1e-6f);
#pragma unroll
    for (int i = 0; i < 4; i++) {
        int c = lane + 32*i;
        xt[(size_t)t*128 + c] = v[i];
        ln[(size_t)t*128 + c] = (v[i]-mu)*rs*gw[c] + bw[c];
    }
}

// ---------------- generic tiled SGEMM: C[M,N] = A[M,K] * B[K,N] -------------
// batched (z), optional per-row bias (per-batch stride), accumulate, relu.
// Requires N%64==0, K%16==0, lda/ldb%4==0. M guarded.
template<bool ACC, bool RELU>
__global__ void gemm_nn(const float* __restrict__ A, int lda, long long sA,
                        const float* __restrict__ B, int ldb, long long sB,
                        float* __restrict__ C, int ldc, long long sC,
                        const float* __restrict__ bias, int sBias,
                        int M, int K)
{
    __shared__ float As[16][65];
    __shared__ float Bs[16][64];
    int zb = blockIdx.z;
    A += sA * zb; B += sB * zb; C += sC * zb;
    int m0 = blockIdx.y << 6, n0 = blockIdx.x << 6;
    int tid = threadIdx.x;
    int tx = tid & 15, ty = tid >> 4;
    int am = tid >> 2, ak = (tid & 3) << 2;
    int bk = tid >> 4, bn = (tid & 15) << 2;
    float acc[4][4] = {};
    for (int k0 = 0; k0 < K; k0 += 16) {
        float4 av = make_float4(0.f,0.f,0.f,0.f);
        if (m0 + am < M) av = *(const float4*)(A + (size_t)(m0+am)*lda + k0 + ak);
        As[ak+0][am] = av.x; As[ak+1][am] = av.y; As[ak+2][am] = av.z; As[ak+3][am] = av.w;
        *(float4*)&Bs[bk][bn] = *(const float4*)(B + (size_t)(k0+bk)*ldb + n0 + bn);
        __syncthreads();
#pragma unroll
        for (int kk = 0; kk < 16; kk++) {
            float a0 = As[kk][ty*4+0], a1 = As[kk][ty*4+1], a2 = As[kk][ty*4+2], a3 = As[kk][ty*4+3];
            float b0 = Bs[kk][tx*4+0], b1 = Bs[kk][tx*4+1], b2 = Bs[kk][tx*4+2], b3 = Bs[kk][tx*4+3];
            acc[0][0]+=a0*b0; acc[0][1]+=a0*b1; acc[0][2]+=a0*b2; acc[0][3]+=a0*b3;
            acc[1][0]+=a1*b0; acc[1][1]+=a1*b1; acc[1][2]+=a1*b2; acc[1][3]+=a1*b3;
            acc[2][0]+=a2*b0; acc[2][1]+=a2*b1; acc[2][2]+=a2*b2; acc[2][3]+=a2*b3;
            acc[3][0]+=a3*b0; acc[3][1]+=a3*b1; acc[3][2]+=a3*b2; acc[3][3]+=a3*b3;
        }
        __syncthreads();
    }
#pragma unroll
    for (int i = 0; i < 4; i++) {
        int m = m0 + ty*4 + i;
        if (m >= M) continue;
        float bi = bias ? bias[(size_t)sBias*zb + m] : 0.f;
#pragma unroll
        for (int j = 0; j < 4; j++) {
            int n = n0 + tx*4 + j;
            float v = acc[i][j] + bi;
            if (ACC) v += C[(size_t)m*ldc + n];
            if (RELU) v = fmaxf(v, 0.f);
            C[(size_t)m*ldc + n] = v;
        }
    }
}

template<bool ACC, bool RELU>
static void launch_gemm(const float* A, int lda, long long sA,
                        const float* B, int ldb, long long sB,
                        float* C, int ldc, long long sC,
                        const float* bias, int sBias,
                        int M, int N, int K, int batch)
{
    dim3 g(N/64, (M+63)/64, batch);
    gemm_nn<ACC,RELU><<<g, 256>>>(A,lda,sA,B,ldb,sB,C,ldc,sC,bias,sBias,M,K);
}

// ---------------- attention: per (b,h,qtile=32) -----------------------------
#define ATTN_SMEM ((32*33 + 64*36 + 64*132 + 32*520)*4)
__global__ void attn_kernel(const float* __restrict__ qb, const float* __restrict__ kb,
                            const float* __restrict__ vb, float* __restrict__ rb)
{
    extern __shared__ float sm[];
    float* Qs = sm;                 // 32 x 33
    float* Kt = Qs + 32*33;         // 64 x 36
    float* Vt = Kt + 64*36;         // 64 x 132
    float* Ss = Vt + 64*132;        // 32 x 520
    int q0 = blockIdx.x << 5;
    int h  = blockIdx.y;
    int b  = blockIdx.z;
    int tid = threadIdx.x;
    int ty = tid >> 3, tx = tid & 7;

    { int e = tid << 2; int row = e >> 5, col = e & 31;
      float4 v = *(const float4*)(qb + ((size_t)(b*512 + q0 + row) << 7) + h*32 + col);
      Qs[row*33+col]=v.x; Qs[row*33+col+1]=v.y; Qs[row*33+col+2]=v.z; Qs[row*33+col+3]=v.w; }
    __syncthreads();

    float qreg[32];
#pragma unroll
    for (int d = 0; d < 32; d++) qreg[d] = Qs[ty*33 + d];
    const float scale = 0.1767766952966369f; // 1/sqrt(32)

    for (int kt = 0; kt < 8; kt++) {
#pragma unroll
        for (int i = 0; i < 2; i++) {
            int e = (tid + i*256) << 2; int row = e >> 5, col = e & 31;
            *(float4*)&Kt[row*36+col] =
                *(const float4*)(kb + ((size_t)(b*512 + kt*64 + row) << 7) + h*32 + col);
        }
        __syncthreads();
#pragma unroll
        for (int i = 0; i < 8; i++) {
            int kv = tx*8 + i;
            const float4* kr = (const float4*)&Kt[kv*36];
            float s = 0.f;
#pragma unroll
            for (int d4 = 0; d4 < 8; d4++) {
                float4 kv4 = kr[d4];
                s += qreg[d4*4+0]*kv4.x + qreg[d4*4+1]*kv4.y + qreg[d4*4+2]*kv4.z + qreg[d4*4+3]*kv4.w;
            }
            Ss[ty*520 + kt*64 + kv] = s * scale;
        }
        __syncthreads();
    }
    // softmax over 512, 8 threads per row
    float mmax = -1e30f;
#pragma unroll 8
    for (int i = 0; i < 64; i++) mmax = fmaxf(mmax, Ss[ty*520 + tx*64 + i]);
    mmax = fmaxf(mmax, __shfl_xor_sync(0xffffffffu, mmax, 1));
    mmax = fmaxf(mmax, __shfl_xor_sync(0xffffffffu, mmax, 2));
    mmax = fmaxf(mmax, __shfl_xor_sync(0xffffffffu, mmax, 4));
    float ssum = 0.f;
#pragma unroll 8
    for (int i = 0; i < 64; i++) {
        float e = __expf(Ss[ty*520 + tx*64 + i] - mmax);
        Ss[ty*520 + tx*64 + i] = e; ssum += e;
    }
    ssum += __shfl_xor_sync(0xffffffffu, ssum, 1);
    ssum += __shfl_xor_sync(0xffffffffu, ssum, 2);
    ssum += __shfl_xor_sync(0xffffffffu, ssum, 4);
    float inv = 1.f / ssum;
#pragma unroll 8
    for (int i = 0; i < 64; i++) Ss[ty*520 + tx*64 + i] *= inv;
    __syncthreads();

    float acc[16] = {};
    for (int kt = 0; kt < 8; kt++) {
#pragma unroll
        for (int i = 0; i < 8; i++) {
            int f4 = tid + i*256; int row = f4 >> 5, c4 = f4 & 31;
            *(float4*)&Vt[row*132 + c4*4] =
                *(const float4*)(vb + ((size_t)(b*512 + kt*64 + row) << 9) + h*128 + c4*4);
        }
        __syncthreads();
        for (int kv = 0; kv < 64; kv++) {
            float p = Ss[ty*520 + kt*64 + kv];
            const float4* vr = (const float4*)&Vt[kv*132 + tx*16];
            float4 v0 = vr[0], v1 = vr[1], v2 = vr[2], v3 = vr[3];
            acc[0]+=p*v0.x; acc[1]+=p*v0.y; acc[2] +=p*v0.z; acc[3] +=p*v0.w;
            acc[4]+=p*v1.x; acc[5]+=p*v1.y; acc[6] +=p*v1.z; acc[7] +=p*v1.w;
            acc[8]+=p*v2.x; acc[9]+=p*v2.y; acc[10]+=p*v2.z; acc[11]+=p*v2.w;
            acc[12]+=p*v3.x; acc[13]+=p*v3.y; acc[14]+=p*v3.z; acc[15]+=p*v3.w;
        }
        __syncthreads();
    }
    float* out = rb + ((size_t)(b*512 + q0 + ty) << 9) + h*128 + tx*16;
#pragma unroll
    for (int i = 0; i < 4; i++)
        *(float4*)(out + i*4) = make_float4(acc[i*4], acc[i*4+1], acc[i*4+2], acc[i*4+3]);
}

// ---------------- circular dilated conv + relu + residual -> states ---------
#define CONV_SMEM ((96*129 + 8*9*128)*4)
__global__ void circconv_kernel(const float* __restrict__ m, const float* __restrict__ w,
                                const float* __restrict__ cb, float* __restrict__ states,
                                int layer, int dil)
{
    extern __shared__ float sm[];
    float (*xs)[129] = (float(*)[129])sm;      // tokens x channels
    float* ws = sm + 96*129;                   // [c(8)][t(9)][o(128)]
    int k0 = blockIdx.x << 6;
    int b  = blockIdx.y;
    int tid = threadIdx.x;
    int span = 64 + 8*dil;

    for (int e = tid; e < span*128; e += 256) {
        int row = e >> 7, c = e & 127;
        int gk = (k0 - 4*dil + row) & 511;
        xs[row][c] = m[((size_t)(b*512 + gk) << 7) + c];
    }
    int to = tid >> 4, tk = tid & 15;
    int ob = to << 3, kb = tk << 2;
    float acc[8][4] = {};

    for (int c0 = 0; c0 < 128; c0 += 8) {
        __syncthreads();
        for (int e = tid; e < 8*9*128; e += 256) {
            int o = e / 72; int r = e - o*72; int c = r / 9; int t = r - c*9;
            ws[(c*9 + t)*128 + o] = w[((size_t)(o*128 + c0 + c))*9 + t];
        }
        __syncthreads();
#pragma unroll
        for (int c = 0; c < 8; c++) {
            int cc = c0 + c;
#pragma unroll
            for (int t = 0; t < 9; t++) {
                const float* wr = &ws[(c*9 + t) << 7];
                float wv[8];
                *(float4*)&wv[0] = *(const float4*)(wr + ob);
                *(float4*)&wv[4] = *(const float4*)(wr + ob + 4);
                int r0 = kb + t*dil;
                float xv[4];
#pragma unroll
                for (int j = 0; j < 4; j++) xv[j] = xs[r0+j][cc];
#pragma unroll
                for (int i = 0; i < 8; i++)
#pragma unroll
                    for (int j = 0; j < 4; j++) acc[i][j] += wv[i]*xv[j];
            }
        }
    }
    float* out = states + ((size_t)(b*8 + layer) << 16);
    const float* res = (layer > 0) ? states + ((size_t)(b*8 + layer-1) << 16) : nullptr;
#pragma unroll
    for (int i = 0; i < 8; i++) {
        int o = ob + i;
        float bias = cb[o];
#pragma unroll
        for (int j = 0; j < 4; j++) {
            int kk = k0 + kb + j;
            float v = fmaxf(acc[i][j] + bias, 0.f);
            if (res) v += res[(size_t)o*512 + kk];
            out[(size_t)o*512 + kk] = v;
        }
    }
}

// ---------------- max over k ------------------------------------------------
__global__ void gmax_kernel(const float* __restrict__ ftmp, float* __restrict__ g)
{
    int w = blockIdx.x*8 + (threadIdx.x >> 5);
    int lane = threadIdx.x & 31;
    const float* row = ftmp + (size_t)w*512;
    float m = -1e30f;
    for (int i = lane; i < 512; i += 32) m = fmaxf(m, row[i]);
#pragma unroll
    for (int o = 16; o; o >>= 1) m = fmaxf(m, __shfl_xor_sync(0xffffffffu, m, o));
    if (lane == 0) g[w] = m;
}

// out[b,o] = bias[o] + W[o, :256] . g[b, :256]
__global__ void dotw_kernel(const float* __restrict__ W, int ldw,
                            const float* __restrict__ bias,
                            const float* __restrict__ g, float* __restrict__ out)
{
    int idx = blockIdx.x*256 + threadIdx.x;
    int b = idx >> 8, o = idx & 255;
    const float* wr = W + (size_t)o*ldw;
    const float* gr = g + b*256;
    float s = bias[o];
#pragma unroll 8
    for (int f = 0; f < 256; f++) s += wr[f]*gr[f];
    out[idx] = s;
}

// dst[n*M+m] = src[m*N+n]
__global__ void transpose_kernel(const float* __restrict__ src, float* __restrict__ dst,
                                 int M, int N, long long sS, long long sD)
{
    __shared__ float tile[32][33];
    int zb = blockIdx.z; src += sS*zb; dst += sD*zb;
    int n0 = blockIdx.x << 5, m0 = blockIdx.y << 5;
    int tx = threadIdx.x & 31, ty = threadIdx.x >> 5;
#pragma unroll
    for (int i = 0; i < 32; i += 8) {
        int m = m0 + ty + i;
        if (m < M && n0 + tx < N) tile[ty+i][tx] = src[(size_t)m*N + n0 + tx];
    }
    __syncthreads();
#pragma unroll
    for (int i = 0; i < 32; i += 8) {
        int n = n0 + ty + i, m = m0 + tx;
        if (n < N && m < M) dst[(size_t)n*M + m] = tile[tx][ty+i];
    }
}

__device__ __forceinline__ float sigf(float x) { return 1.f/(1.f + __expf(-x)); }

__global__ void lstm_kernel(const float* __restrict__ gates, const float* __restrict__ b_ih,
                            const float* __restrict__ b_hh, const float* __restrict__ c0,
                            float* __restrict__ h_out, float* __restrict__ c_out,
                            float* __restrict__ ocf)
{
    int idx = blockIdx.x*256 + threadIdx.x;
    int t = idx >> 8, c = idx & 255;
    const float* gr = gates + (size_t)t*1024;
    float gi = gr[c]       + b_ih[c]       + b_hh[c];
    float gf = gr[256 + c] + b_ih[256 + c] + b_hh[256 + c];
    float gg = gr[512 + c] + b_ih[512 + c] + b_hh[512 + c];
    float go = gr[768 + c] + b_ih[768 + c] + b_hh[768 + c];
    float cn = sigf(gf)*c0[idx] + sigf(gi)*tanhf(gg);
    float hn = sigf(go)*tanhf(cn);
    h_out[idx] = hn;
    c_out[idx] = cn;
    int b = t >> 9, k = t & 511;
    ocf[((size_t)(b*256 + c) << 9) + k] = hn;
}

// ---------------- host orchestration ---------------------------------------
static float* sym(const void* s) { void* p = nullptr; cudaGetSymbolAddress(&p, s); return (float*)p; }

extern "C" void kernel_launch(void* const* d_in, const int* in_sizes, int n_in,
                              void* d_out, int out_size)
{
    (void)in_sizes; (void)n_in; (void)out_size;
    static const int DIL[8] = {1,1,1,1,2,2,4,4};
    const float* x    = (const float*)d_in[0];
    const float* h0   = (const float*)d_in[1];
    const float* c0   = (const float*)d_in[2];
    const float* ln_g = (const float*)d_in[3];
    const float* ln_b = (const float*)d_in[4];
    const float* Wq   = (const float*)d_in[5];
    const float* Wk   = (const float*)d_in[6];
    const float* Wv   = (const float*)d_in[7];
    const float* Ww   = (const float*)d_in[8];
    const float* Wa   = (const float*)d_in[9];
    const float* cw   = (const float*)d_in[10];
    const float* cb   = (const float*)d_in[11];
    const float* fus_w= (const float*)d_in[12];
    const float* fus_b= (const float*)d_in[13];
    const float* rs_w = (const float*)d_in[14];
    const float* rs_b = (const float*)d_in[15];
    const float* W_ih = (const float*)d_in[16];
    const float* W_hh = (const float*)d_in[17];
    const float* b_ih = (const float*)d_in[18];
    const float* b_hh = (const float*)d_in[19];
    const float* p1_w = (const float*)d_in[20];
    const float* p1_b = (const float*)d_in[21];
    const float* p2_w = (const float*)d_in[22];
    const float* p2_b = (const float*)d_in[23];
    const float* p3_w = (const float*)d_in[24];
    const float* p3_b = (const float*)d_in[25];

    float *xt = sym(d_xt), *lnb = sym(d_ln), *qb = sym(d_q), *kb = sym(d_k);
    float *vb = sym(d_v), *rb = sym(d_r), *rwb = sym(d_rw), *mhab = sym(d_mha);
    float *states = sym(d_states), *ftmp = sym(d_ftmp), *g = sym(d_g);
    float *gb = sym(d_gb), *pb = sym(d_pb), *rnn = sym(d_rnn), *it = sym(d_it);
    float *wTih = sym(d_wTih), *wThh = sym(d_wThh), *gates = sym(d_gates);
    float *ocf = sym(d_ocf), *p1o = sym(d_p1), *p2o = sym(d_p2);

    (void)cudaFuncSetAttribute(attn_kernel, cudaFuncAttributeMaxDynamicSharedMemorySize, ATTN_SMEM);
    (void)cudaFuncSetAttribute(circconv_kernel, cudaFuncAttributeMaxDynamicSharedMemorySize, CONV_SMEM);

    float* outp  = (float*)d_out;
    float* h_out = outp + BATCH*2*SEQ;
    float* c_out = h_out + (size_t)TOK*RNN;

    for (int l = 0; l < NL; l++) {
        const float* hin = (l == 0) ? x : states + (size_t)(l-1)*CH*SEQ;
        long long bStride = (l == 0) ? (long long)CH*SEQ : (long long)NL*CH*SEQ;
        ln_kernel<<<TOK/8, 256>>>(hin, bStride, ln_g + l*CH, ln_b + l*CH, xt, lnb);

        launch_gemm<false,false>(lnb,128,0, Wq + (size_t)l*128*128,128,0, qb,128,0, nullptr,0, TOK,128,128, 1);
        launch_gemm<false,false>(lnb,128,0, Wk + (size_t)l*128*128,128,0, kb,128,0, nullptr,0, TOK,128,128, 1);
        launch_gemm<false,false>(lnb,128,0, Wv + (size_t)l*128*512,512,0, vb,512,0, nullptr,0, TOK,512,128, 1);

        attn_kernel<<<dim3(16,4,64), 256, ATTN_SMEM>>>(qb, kb, vb, rb);

        launch_gemm<false,false>(rb,512,0, Ww + (size_t)l*512*128,128,0, rwb,128,0, nullptr,0, TOK,128,512, 1);
        launch_gemm<false,false>(rwb,128,0, Wa + (size_t)l*256*128,128,0, mhab,128,0, nullptr,0, TOK,128,128, 1);
        launch_gemm<true ,false>(xt ,128,0, Wa + (size_t)l*256*128 + 128*128,128,0, mhab,128,0, nullptr,0, TOK,128,128, 1);

        circconv_kernel<<<dim3(8,64), 256, CONV_SMEM>>>(mhab, cw + (size_t)l*128*128*9, cb + l*128,
                                                        states, l, DIL[l]);
    }

    // fusion gate: g[b,o] = max_k (fus_w @ state + fus_b)
    launch_gemm<false,false>(fus_w,1024,0, states,512,(long long)NL*CH*SEQ,
                             ftmp,512,(long long)256*SEQ, fus_b,0, 256,512,1024, BATCH);
    gmax_kernel<<<BATCH*256/8, 256>>>(ftmp, g);

    // rnn_in = rs_w[:, :256] @ g (per-b bias) + rs_w[:, 256:] @ states
    dotw_kernel<<<BATCH, 256>>>(rs_w, 1280, rs_b, g, gb);
    launch_gemm<false,false>(rs_w + 256,1280,0, states,512,(long long)NL*CH*SEQ,
                             rnn,512,(long long)256*SEQ, gb,256, 256,512,1024, BATCH);

    // LSTM single step over 32768 tokens
    transpose_kernel<<<dim3(16,8,BATCH), 256>>>(rnn, it, 256, 512, (long long)256*SEQ, (long long)256*SEQ);
    transpose_kernel<<<dim3(8,32,1), 256>>>(W_ih, wTih, 1024, 256, 0, 0);
    transpose_kernel<<<dim3(8,32,1), 256>>>(W_hh, wThh, 1024, 256, 0, 0);
    launch_gemm<false,false>(it,256,0, wTih,1024,0, gates,1024,0, nullptr,0, TOK,1024,256, 1);
    launch_gemm<true ,false>(h0,256,0, wThh,1024,0, gates,1024,0, nullptr,0, TOK,1024,256, 1);
    lstm_kernel<<<TOK, 256>>>(gates, b_ih, b_hh, c0, h_out, c_out, ocf);

    // p1 = relu(p1_w[:, :256]@o + p1_w[:,256:512]@g + p1_w[:,512:]@states + p1_b)
    dotw_kernel<<<BATCH, 256>>>(p1_w + 256, 1536, p1_b, g, pb);
    launch_gemm<false,false>(p1_w,1536,0, ocf,512,(long long)256*SEQ,
                             p1o,512,(long long)256*SEQ, pb,256, 256,512,256, BATCH);
    launch_gemm<true ,true >(p1_w + 512,1536,0, states,512,(long long)NL*CH*SEQ,
                             p1o,512,(long long)256*SEQ, nullptr,0, 256,512,1024, BATCH);
    // p2, p3
    launch_gemm<false,true >(p2_w,256,0, p1o,512,(long long)256*SEQ,
                             p2o,512,(long long)64*SEQ, p2_b,0, 64,512,256, BATCH);
    launch_gemm<false,false>(p3_w,64,0, p2o,512,(long long)64*SEQ,
                             outp,512,(long long)2*SEQ, p3_b,0, 2,512,64, BATCH);
}

// round 4
// speedup vs baseline: 1.0002x; 1.0002x over previous
#include <cuda_runtime.h>
#include <cstdio>

#define BATCH 64
#define SEQ   512
#define CH    128
#define NHEAD 4
#define DHEAD 32
#define NL    8
#define RNN   256
#define TOK   (BATCH*SEQ)          // 32768

// ---------------- scratch (static __device__, no allocations) ----------------
__device__ float d_xt   [TOK*CH];
__device__ float d_ln   [TOK*CH];
__device__ float d_q    [TOK*CH];
__device__ float d_k    [TOK*CH];
__device__ float d_v    [TOK*512];
__device__ float d_r    [TOK*512];
__device__ float d_rw   [TOK*CH];
__device__ float d_mha  [TOK*CH];
__device__ float d_states[BATCH*NL*CH*SEQ];     // (b, layer, c, k) == (B,1024,512)
__device__ float d_ftmp [BATCH*256*SEQ];
__device__ float d_g    [BATCH*256];
__device__ float d_gb   [BATCH*256];
__device__ float d_pb   [BATCH*256];
__device__ float d_rnn  [BATCH*256*SEQ];
__device__ float d_it   [TOK*256];
__device__ float d_wTih [256*1024];
__device__ float d_wThh [256*1024];
__device__ float d_gates[TOK*1024];
__device__ float d_ocf  [BATCH*256*SEQ];
__device__ float d_p1   [BATCH*256*SEQ];
__device__ float d_p2   [BATCH*64*SEQ];

// ---------------- LayerNorm + transpose: (B,C,K) -> tokens (T,128) ----------
__global__ void ln_kernel(const float* __restrict__ h, long long bStride,
                          const float* __restrict__ gw, const float* __restrict__ bw,
                          float* __restrict__ xt, float* __restrict__ ln)
{
    int warp = threadIdx.x >> 5, lane = threadIdx.x & 31;
    int t = blockIdx.x * 8 + warp;
    int b = t >> 9, k = t & 511;
    const float* base = h + (size_t)b * bStride + k;
    float v[4]; float s = 0.f;
#pragma unroll
    for (int i = 0; i < 4; i++) { int c = lane + 32*i; v[i] = base[(size_t)c*512]; s += v[i]; }
#pragma unroll
    for (int o = 16; o; o >>= 1) s += __shfl_xor_sync(0xffffffffu, s, o);
    float mu = s * (1.f/128.f);
    float var = 0.f;
#pragma unroll
    for (int i = 0; i < 4; i++) { float d = v[i]-mu; var += d*d; }
#pragma unroll
    for (int o = 16; o; o >>= 1) var += __shfl_xor_sync(0xffffffffu, var, o);
    float rs = rsqrtf(var * (1.f/128.f) + 1e-6f);
#pragma unroll
    for (int i = 0; i < 4; i++) {
        int c = lane + 32*i;
        xt[(size_t)t*128 + c] = v[i];
        ln[(size_t)t*128 + c] = (v[i]-mu)*rs*gw[c] + bw[c];
    }
}

// ---------------- generic tiled SGEMM: C[M,N] = A[M,K] * B[K,N] -------------
// batched (z), optional per-row bias (per-batch stride), accumulate, relu.
// Requires N%64==0, K%16==0, lda/ldb%4==0. M guarded.
template<bool ACC, bool RELU>
__global__ void gemm_nn(const float* __restrict__ A, int lda, long long sA,
                        const float* __restrict__ B, int ldb, long long sB,
                        float* __restrict__ C, int ldc, long long sC,
                        const float* __restrict__ bias, int sBias,
                        int M, int K)
{
    __shared__ float As[16][65];
    __shared__ float Bs[16][64];
    int zb = blockIdx.z;
    A += sA * zb; B += sB * zb; C += sC * zb;
    int m0 = blockIdx.y << 6, n0 = blockIdx.x << 6;
    int tid = threadIdx.x;
    int tx = tid & 15, ty = tid >> 4;
    int am = tid >> 2, ak = (tid & 3) << 2;
    int bk = tid >> 4, bn = (tid & 15) << 2;
    float acc[4][4] = {};
    for (int k0 = 0; k0 < K; k0 += 16) {
        float4 av = make_float4(0.f,0.f,0.f,0.f);
        if (m0 + am < M) av = *(const float4*)(A + (size_t)(m0+am)*lda + k0 + ak);
        As[ak+0][am] = av.x; As[ak+1][am] = av.y; As[ak+2][am] = av.z; As[ak+3][am] = av.w;
        *(float4*)&Bs[bk][bn] = *(const float4*)(B + (size_t)(k0+bk)*ldb + n0 + bn);
        __syncthreads();
#pragma unroll
        for (int kk = 0; kk < 16; kk++) {
            float a0 = As[kk][ty*4+0], a1 = As[kk][ty*4+1], a2 = As[kk][ty*4+2], a3 = As[kk][ty*4+3];
            float b0 = Bs[kk][tx*4+0], b1 = Bs[kk][tx*4+1], b2 = Bs[kk][tx*4+2], b3 = Bs[kk][tx*4+3];
            acc[0][0]+=a0*b0; acc[0][1]+=a0*b1; acc[0][2]+=a0*b2; acc[0][3]+=a0*b3;
            acc[1][0]+=a1*b0; acc[1][1]+=a1*b1; acc[1][2]+=a1*b2; acc[1][3]+=a1*b3;
            acc[2][0]+=a2*b0; acc[2][1]+=a2*b1; acc[2][2]+=a2*b2; acc[2][3]+=a2*b3;
            acc[3][0]+=a3*b0; acc[3][1]+=a3*b1; acc[3][2]+=a3*b2; acc[3][3]+=a3*b3;
        }
        __syncthreads();
    }
#pragma unroll
    for (int i = 0; i < 4; i++) {
        int m = m0 + ty*4 + i;
        if (m >= M) continue;
        float bi = bias ? bias[(size_t)sBias*zb + m] : 0.f;
#pragma unroll
        for (int j = 0; j < 4; j++) {
            int n = n0 + tx*4 + j;
            float v = acc[i][j] + bi;
            if (ACC) v += C[(size_t)m*ldc + n];
            if (RELU) v = fmaxf(v, 0.f);
            C[(size_t)m*ldc + n] = v;
        }
    }
}

template<bool ACC, bool RELU>
static void launch_gemm(const float* A, int lda, long long sA,
                        const float* B, int ldb, long long sB,
                        float* C, int ldc, long long sC,
                        const float* bias, int sBias,
                        int M, int N, int K, int batch)
{
    dim3 g(N/64, (M+63)/64, batch);
    gemm_nn<ACC,RELU><<<g, 256>>>(A,lda,sA,B,ldb,sB,C,ldc,sC,bias,sBias,M,K);
}

// ---------------- attention: per (b,h,qtile=32) -----------------------------
#define ATTN_SMEM ((32*33 + 64*36 + 64*132 + 32*520)*4)
__global__ void attn_kernel(const float* __restrict__ qb, const float* __restrict__ kb,
                            const float* __restrict__ vb, float* __restrict__ rb)
{
    extern __shared__ float sm[];
    float* Qs = sm;                 // 32 x 33
    float* Kt = Qs + 32*33;         // 64 x 36
    float* Vt = Kt + 64*36;         // 64 x 132
    float* Ss = Vt + 64*132;        // 32 x 520
    int q0 = blockIdx.x << 5;
    int h  = blockIdx.y;
    int b  = blockIdx.z;
    int tid = threadIdx.x;
    int ty = tid >> 3, tx = tid & 7;

    { int e = tid << 2; int row = e >> 5, col = e & 31;
      float4 v = *(const float4*)(qb + ((size_t)(b*512 + q0 + row) << 7) + h*32 + col);
      Qs[row*33+col]=v.x; Qs[row*33+col+1]=v.y; Qs[row*33+col+2]=v.z; Qs[row*33+col+3]=v.w; }
    __syncthreads();

    float qreg[32];
#pragma unroll
    for (int d = 0; d < 32; d++) qreg[d] = Qs[ty*33 + d];
    const float scale = 0.1767766952966369f; // 1/sqrt(32)

    for (int kt = 0; kt < 8; kt++) {
#pragma unroll
        for (int i = 0; i < 2; i++) {
            int e = (tid + i*256) << 2; int row = e >> 5, col = e & 31;
            *(float4*)&Kt[row*36+col] =
                *(const float4*)(kb + ((size_t)(b*512 + kt*64 + row) << 7) + h*32 + col);
        }
        __syncthreads();
#pragma unroll
        for (int i = 0; i < 8; i++) {
            int kv = tx*8 + i;
            const float4* kr = (const float4*)&Kt[kv*36];
            float s = 0.f;
#pragma unroll
            for (int d4 = 0; d4 < 8; d4++) {
                float4 kv4 = kr[d4];
                s += qreg[d4*4+0]*kv4.x + qreg[d4*4+1]*kv4.y + qreg[d4*4+2]*kv4.z + qreg[d4*4+3]*kv4.w;
            }
            Ss[ty*520 + kt*64 + kv] = s * scale;
        }
        __syncthreads();
    }
    // softmax over 512, 8 threads per row
    float mmax = -1e30f;
#pragma unroll 8
    for (int i = 0; i < 64; i++) mmax = fmaxf(mmax, Ss[ty*520 + tx*64 + i]);
    mmax = fmaxf(mmax, __shfl_xor_sync(0xffffffffu, mmax, 1));
    mmax = fmaxf(mmax, __shfl_xor_sync(0xffffffffu, mmax, 2));
    mmax = fmaxf(mmax, __shfl_xor_sync(0xffffffffu, mmax, 4));
    float ssum = 0.f;
#pragma unroll 8
    for (int i = 0; i < 64; i++) {
        float e = __expf(Ss[ty*520 + tx*64 + i] - mmax);
        Ss[ty*520 + tx*64 + i] = e; ssum += e;
    }
    ssum += __shfl_xor_sync(0xffffffffu, ssum, 1);
    ssum += __shfl_xor_sync(0xffffffffu, ssum, 2);
    ssum += __shfl_xor_sync(0xffffffffu, ssum, 4);
    float inv = 1.f / ssum;
#pragma unroll 8
    for (int i = 0; i < 64; i++) Ss[ty*520 + tx*64 + i] *= inv;
    __syncthreads();

    float acc[16] = {};
    for (int kt = 0; kt < 8; kt++) {
#pragma unroll
        for (int i = 0; i < 8; i++) {
            int f4 = tid + i*256; int row = f4 >> 5, c4 = f4 & 31;
            *(float4*)&Vt[row*132 + c4*4] =
                *(const float4*)(vb + ((size_t)(b*512 + kt*64 + row) << 9) + h*128 + c4*4);
        }
        __syncthreads();
        for (int kv = 0; kv < 64; kv++) {
            float p = Ss[ty*520 + kt*64 + kv];
            const float4* vr = (const float4*)&Vt[kv*132 + tx*16];
            float4 v0 = vr[0], v1 = vr[1], v2 = vr[2], v3 = vr[3];
            acc[0]+=p*v0.x; acc[1]+=p*v0.y; acc[2] +=p*v0.z; acc[3] +=p*v0.w;
            acc[4]+=p*v1.x; acc[5]+=p*v1.y; acc[6] +=p*v1.z; acc[7] +=p*v1.w;
            acc[8]+=p*v2.x; acc[9]+=p*v2.y; acc[10]+=p*v2.z; acc[11]+=p*v2.w;
            acc[12]+=p*v3.x; acc[13]+=p*v3.y; acc[14]+=p*v3.z; acc[15]+=p*v3.w;
        }
        __syncthreads();
    }
    float* out = rb + ((size_t)(b*512 + q0 + ty) << 9) + h*128 + tx*16;
#pragma unroll
    for (int i = 0; i < 4; i++)
        *(float4*)(out + i*4) = make_float4(acc[i*4], acc[i*4+1], acc[i*4+2], acc[i*4+3]);
}

// ---------------- circular dilated conv + relu + residual -> states ---------
#define CONV_SMEM ((96*129 + 8*9*128)*4)
__global__ void circconv_kernel(const float* __restrict__ m, const float* __restrict__ w,
                                const float* __restrict__ cb, float* __restrict__ states,
                                int layer, int dil)
{
    extern __shared__ float sm[];
    float (*xs)[129] = (float(*)[129])sm;      // tokens x channels
    float* ws = sm + 96*129;                   // [c(8)][t(9)][o(128)]
    int k0 = blockIdx.x << 6;
    int b  = blockIdx.y;
    int tid = threadIdx.x;
    int span = 64 + 8*dil;

    for (int e = tid; e < span*128; e += 256) {
        int row = e >> 7, c = e & 127;
        int gk = (k0 - 4*dil + row) & 511;
        xs[row][c] = m[((size_t)(b*512 + gk) << 7) + c];
    }
    int to = tid >> 4, tk = tid & 15;
    int ob = to << 3, kb = tk << 2;
    float acc[8][4] = {};

    for (int c0 = 0; c0 < 128; c0 += 8) {
        __syncthreads();
        for (int e = tid; e < 8*9*128; e += 256) {
            int o = e / 72; int r = e - o*72; int c = r / 9; int t = r - c*9;
            ws[(c*9 + t)*128 + o] = w[((size_t)(o*128 + c0 + c))*9 + t];
        }
        __syncthreads();
#pragma unroll
        for (int c = 0; c < 8; c++) {
            int cc = c0 + c;
#pragma unroll
            for (int t = 0; t < 9; t++) {
                const float* wr = &ws[(c*9 + t) << 7];
                float wv[8];
                *(float4*)&wv[0] = *(const float4*)(wr + ob);
                *(float4*)&wv[4] = *(const float4*)(wr + ob + 4);
                int r0 = kb + t*dil;
                float xv[4];
#pragma unroll
                for (int j = 0; j < 4; j++) xv[j] = xs[r0+j][cc];
#pragma unroll
                for (int i = 0; i < 8; i++)
#pragma unroll
                    for (int j = 0; j < 4; j++) acc[i][j] += wv[i]*xv[j];
            }
        }
    }
    float* out = states + ((size_t)(b*8 + layer) << 16);
    const float* res = (layer > 0) ? states + ((size_t)(b*8 + layer-1) << 16) : nullptr;
#pragma unroll
    for (int i = 0; i < 8; i++) {
        int o = ob + i;
        float bias = cb[o];
#pragma unroll
        for (int j = 0; j < 4; j++) {
            int kk = k0 + kb + j;
            float v = fmaxf(acc[i][j] + bias, 0.f);
            if (res) v += res[(size_t)o*512 + kk];
            out[(size_t)o*512 + kk] = v;
        }
    }
}

// ---------------- max over k ------------------------------------------------
__global__ void gmax_kernel(const float* __restrict__ ftmp, float* __restrict__ g)
{
    int w = blockIdx.x*8 + (threadIdx.x >> 5);
    int lane = threadIdx.x & 31;
    const float* row = ftmp + (size_t)w*512;
    float m = -1e30f;
    for (int i = lane; i < 512; i += 32) m = fmaxf(m, row[i]);
#pragma unroll
    for (int o = 16; o; o >>= 1) m = fmaxf(m, __shfl_xor_sync(0xffffffffu, m, o));
    if (lane == 0) g[w] = m;
}

// out[b,o] = bias[o] + W[o, :256] . g[b, :256]
__global__ void dotw_kernel(const float* __restrict__ W, int ldw,
                            const float* __restrict__ bias,
                            const float* __restrict__ g, float* __restrict__ out)
{
    int idx = blockIdx.x*256 + threadIdx.x;
    int b = idx >> 8, o = idx & 255;
    const float* wr = W + (size_t)o*ldw;
    const float* gr = g + b*256;
    float s = bias[o];
#pragma unroll 8
    for (int f = 0; f < 256; f++) s += wr[f]*gr[f];
    out[idx] = s;
}

// dst[n*M+m] = src[m*N+n]
__global__ void transpose_kernel(const float* __restrict__ src, float* __restrict__ dst,
                                 int M, int N, long long sS, long long sD)
{
    __shared__ float tile[32][33];
    int zb = blockIdx.z; src += sS*zb; dst += sD*zb;
    int n0 = blockIdx.x << 5, m0 = blockIdx.y << 5;
    int tx = threadIdx.x & 31, ty = threadIdx.x >> 5;
#pragma unroll
    for (int i = 0; i < 32; i += 8) {
        int m = m0 + ty + i;
        if (m < M && n0 + tx < N) tile[ty+i][tx] = src[(size_t)m*N + n0 + tx];
    }
    __syncthreads();
#pragma unroll
    for (int i = 0; i < 32; i += 8) {
        int n = n0 + ty + i, m = m0 + tx;
        if (n < N && m < M) dst[(size_t)n*M + m] = tile[tx][ty+i];
    }
}

__device__ __forceinline__ float sigf(float x) { return 1.f/(1.f + __expf(-x)); }

__global__ void lstm_kernel(const float* __restrict__ gates, const float* __restrict__ b_ih,
                            const float* __restrict__ b_hh, const float* __restrict__ c0,
                            float* __restrict__ h_out, float* __restrict__ c_out,
                            float* __restrict__ ocf)
{
    int idx = blockIdx.x*256 + threadIdx.x;
    int t = idx >> 8, c = idx & 255;
    const float* gr = gates + (size_t)t*1024;
    float gi = gr[c]       + b_ih[c]       + b_hh[c];
    float gf = gr[256 + c] + b_ih[256 + c] + b_hh[256 + c];
    float gg = gr[512 + c] + b_ih[512 + c] + b_hh[512 + c];
    float go = gr[768 + c] + b_ih[768 + c] + b_hh[768 + c];
    float cn = sigf(gf)*c0[idx] + sigf(gi)*tanhf(gg);
    float hn = sigf(go)*tanhf(cn);
    h_out[idx] = hn;
    c_out[idx] = cn;
    int b = t >> 9, k = t & 511;
    ocf[((size_t)(b*256 + c) << 9) + k] = hn;
}

// ---------------- host orchestration ---------------------------------------
static float* sym(const void* s) { void* p = nullptr; cudaGetSymbolAddress(&p, s); return (float*)p; }

extern "C" void kernel_launch(void* const* d_in, const int* in_sizes, int n_in,
                              void* d_out, int out_size)
{
    (void)in_sizes; (void)n_in; (void)out_size;
    static const int DIL[8] = {1,1,1,1,2,2,4,4};
    const float* x    = (const float*)d_in[0];
    const float* h0   = (const float*)d_in[1];
    const float* c0   = (const float*)d_in[2];
    const float* ln_g = (const float*)d_in[3];
    const float* ln_b = (const float*)d_in[4];
    const float* Wq   = (const float*)d_in[5];
    const float* Wk   = (const float*)d_in[6];
    const float* Wv   = (const float*)d_in[7];
    const float* Ww   = (const float*)d_in[8];
    const float* Wa   = (const float*)d_in[9];
    const float* cw   = (const float*)d_in[10];
    const float* cb   = (const float*)d_in[11];
    const float* fus_w= (const float*)d_in[12];
    const float* fus_b= (const float*)d_in[13];
    const float* rs_w = (const float*)d_in[14];
    const float* rs_b = (const float*)d_in[15];
    const float* W_ih = (const float*)d_in[16];
    const float* W_hh = (const float*)d_in[17];
    const float* b_ih = (const float*)d_in[18];
    const float* b_hh = (const float*)d_in[19];
    const float* p1_w = (const float*)d_in[20];
    const float* p1_b = (const float*)d_in[21];
    const float* p2_w = (const float*)d_in[22];
    const float* p2_b = (const float*)d_in[23];
    const float* p3_w = (const float*)d_in[24];
    const float* p3_b = (const float*)d_in[25];

    float *xt = sym(d_xt), *lnb = sym(d_ln), *qb = sym(d_q), *kb = sym(d_k);
    float *vb = sym(d_v), *rb = sym(d_r), *rwb = sym(d_rw), *mhab = sym(d_mha);
    float *states = sym(d_states), *ftmp = sym(d_ftmp), *g = sym(d_g);
    float *gb = sym(d_gb), *pb = sym(d_pb), *rnn = sym(d_rnn), *it = sym(d_it);
    float *wTih = sym(d_wTih), *wThh = sym(d_wThh), *gates = sym(d_gates);
    float *ocf = sym(d_ocf), *p1o = sym(d_p1), *p2o = sym(d_p2);

    (void)cudaFuncSetAttribute(attn_kernel, cudaFuncAttributeMaxDynamicSharedMemorySize, ATTN_SMEM);
    (void)cudaFuncSetAttribute(circconv_kernel, cudaFuncAttributeMaxDynamicSharedMemorySize, CONV_SMEM);

    float* outp  = (float*)d_out;
    float* h_out = outp + BATCH*2*SEQ;
    float* c_out = h_out + (size_t)TOK*RNN;

    for (int l = 0; l < NL; l++) {
        const float* hin = (l == 0) ? x : states + (size_t)(l-1)*CH*SEQ;
        long long bStride = (l == 0) ? (long long)CH*SEQ : (long long)NL*CH*SEQ;
        ln_kernel<<<TOK/8, 256>>>(hin, bStride, ln_g + l*CH, ln_b + l*CH, xt, lnb);

        launch_gemm<false,false>(lnb,128,0, Wq + (size_t)l*128*128,128,0, qb,128,0, nullptr,0, TOK,128,128, 1);
        launch_gemm<false,false>(lnb,128,0, Wk + (size_t)l*128*128,128,0, kb,128,0, nullptr,0, TOK,128,128, 1);
        launch_gemm<false,false>(lnb,128,0, Wv + (size_t)l*128*512,512,0, vb,512,0, nullptr,0, TOK,512,128, 1);

        attn_kernel<<<dim3(16,4,64), 256, ATTN_SMEM>>>(qb, kb, vb, rb);

        launch_gemm<false,false>(rb,512,0, Ww + (size_t)l*512*128,128,0, rwb,128,0, nullptr,0, TOK,128,512, 1);
        launch_gemm<false,false>(rwb,128,0, Wa + (size_t)l*256*128,128,0, mhab,128,0, nullptr,0, TOK,128,128, 1);
        launch_gemm<true ,false>(xt ,128,0, Wa + (size_t)l*256*128 + 128*128,128,0, mhab,128,0, nullptr,0, TOK,128,128, 1);

        circconv_kernel<<<dim3(8,64), 256, CONV_SMEM>>>(mhab, cw + (size_t)l*128*128*9, cb + l*128,
                                                        states, l, DIL[l]);
    }

    // fusion gate: g[b,o] = max_k (fus_w @ state + fus_b)
    launch_gemm<false,false>(fus_w,1024,0, states,512,(long long)NL*CH*SEQ,
                             ftmp,512,(long long)256*SEQ, fus_b,0, 256,512,1024, BATCH);
    gmax_kernel<<<BATCH*256/8, 256>>>(ftmp, g);

    // rnn_in = rs_w[:, :256] @ g (per-b bias) + rs_w[:, 256:] @ states
    dotw_kernel<<<BATCH, 256>>>(rs_w, 1280, rs_b, g, gb);
    launch_gemm<false,false>(rs_w + 256,1280,0, states,512,(long long)NL*CH*SEQ,
                             rnn,512,(long long)256*SEQ, gb,256, 256,512,1024, BATCH);

    // LSTM single step over 32768 tokens
    transpose_kernel<<<dim3(16,8,BATCH), 256>>>(rnn, it, 256, 512, (long long)256*SEQ, (long long)256*SEQ);
    transpose_kernel<<<dim3(8,32,1), 256>>>(W_ih, wTih, 1024, 256, 0, 0);
    transpose_kernel<<<dim3(8,32,1), 256>>>(W_hh, wThh, 1024, 256, 0, 0);
    launch_gemm<false,false>(it,256,0, wTih,1024,0, gates,1024,0, nullptr,0, TOK,1024,256, 1);
    launch_gemm<true ,false>(h0,256,0, wThh,1024,0, gates,1024,0, nullptr,0, TOK,1024,256, 1);
    lstm_kernel<<<TOK, 256>>>(gates, b_ih, b_hh, c0, h_out, c_out, ocf);

    // p1 = relu(p1_w[:, :256]@o + p1_w[:,256:512]@g + p1_w[:,512:]@states + p1_b)
    dotw_kernel<<<BATCH, 256>>>(p1_w + 256, 1536, p1_b, g, pb);
    launch_gemm<false,false>(p1_w,1536,0, ocf,512,(long long)256*SEQ,
                             p1o,512,(long long)256*SEQ, pb,256, 256,512,256, BATCH);
    launch_gemm<true ,true >(p1_w + 512,1536,0, states,512,(long long)NL*CH*SEQ,
                             p1o,512,(long long)256*SEQ, nullptr,0, 256,512,1024, BATCH);
    // p2, p3
    launch_gemm<false,true >(p2_w,256,0, p1o,512,(long long)256*SEQ,
                             p2o,512,(long long)64*SEQ, p2_b,0, 64,512,256, BATCH);
    launch_gemm<false,false>(p3_w,64,0, p2o,512,(long long)64*SEQ,
                             outp,512,(long long)2*SEQ, p3_b,0, 2,512,64, BATCH);
}